// round 1
// baseline (speedup 1.0000x reference)
#include <cuda_runtime.h>

#define S_LEN 2048
#define NH 8
#define DA 64
#define DM 512
#define BATCH 2

// Scratch (device globals; no allocation allowed)
__device__ float g_bias[(size_t)BATCH * S_LEN * S_LEN];      // 33.5 MB
__device__ float g_Q[(size_t)BATCH * NH * S_LEN * DA];       // 8 MB
__device__ float g_K[(size_t)BATCH * NH * S_LEN * DA];       // 8 MB
__device__ float g_V[(size_t)BATCH * NH * S_LEN * DA];       // 8 MB
__device__ float g_O[(size_t)BATCH * S_LEN * DM];            // 8 MB

__device__ __forceinline__ unsigned f2t(float x) {
    unsigned u;
    asm("cvt.rna.tf32.f32 %0, %1;" : "=r"(u) : "f"(x));
    return u;
}

__device__ __forceinline__ void mma8(float* c, const unsigned* a, unsigned b0, unsigned b1) {
    asm volatile(
        "mma.sync.aligned.m16n8k8.row.col.f32.tf32.tf32.f32 "
        "{%0,%1,%2,%3},{%4,%5,%6,%7},{%8,%9},{%0,%1,%2,%3};"
        : "+f"(c[0]), "+f"(c[1]), "+f"(c[2]), "+f"(c[3])
        : "r"(a[0]), "r"(a[1]), "r"(a[2]), "r"(a[3]), "r"(b0), "r"(b1));
}

// ---------------------------------------------------------------------------
// Kernel 1: bias[b,s,t] = dot(top[b,s,t,0:16], top_w) + top_b   (HBM-bound)
// ---------------------------------------------------------------------------
__global__ __launch_bounds__(256) void k_bias(const float* __restrict__ top,
                                              const float* __restrict__ tw,
                                              const float* __restrict__ tb) {
    size_t i = (size_t)blockIdx.x * blockDim.x + threadIdx.x;
    const size_t total = (size_t)BATCH * S_LEN * S_LEN;
    if (i >= total) return;
    const float4* t = reinterpret_cast<const float4*>(top) + i * 4;
    float4 w0 = __ldg(reinterpret_cast<const float4*>(tw) + 0);
    float4 w1 = __ldg(reinterpret_cast<const float4*>(tw) + 1);
    float4 w2 = __ldg(reinterpret_cast<const float4*>(tw) + 2);
    float4 w3 = __ldg(reinterpret_cast<const float4*>(tw) + 3);
    float4 a = t[0], b = t[1], c = t[2], d = t[3];
    float s = a.x * w0.x + a.y * w0.y + a.z * w0.z + a.w * w0.w
            + b.x * w1.x + b.y * w1.y + b.z * w1.z + b.w * w1.w
            + c.x * w2.x + c.y * w2.y + c.z * w2.z + c.w * w2.w
            + d.x * w3.x + d.y * w3.y + d.z * w3.z + d.w * w3.w;
    g_bias[i] = s + tb[0];
}

// ---------------------------------------------------------------------------
// Kernel 2/4: TF32 tensor-core GEMM. out[n,c] = sum_k A[n,k] * W[c,k] + bias[c]
// M=4096, N=512, K=512. BM=128, BN=64, BK=32, 256 threads (8 warps, 4x2).
// MODE 0: QKV (grid.z selects w/b/out, head-layout epilogue)
// MODE 1: O-proj (plain row-major epilogue to out)
// ---------------------------------------------------------------------------
template <int MODE>
__global__ __launch_bounds__(256) void k_gemm(
    const float* __restrict__ A,
    const float* __restrict__ Wq, const float* __restrict__ Bq,
    const float* __restrict__ Wk, const float* __restrict__ Bk,
    const float* __restrict__ Wv, const float* __restrict__ Bv,
    float* __restrict__ out) {
    __shared__ unsigned As[128][33];
    __shared__ unsigned Bs[64][33];

    const float* Ap = A ? A : g_O;
    const float* W;
    const float* bb;
    float* op;
    if (MODE == 0) {
        int z = blockIdx.z;
        W  = (z == 0) ? Wq : (z == 1) ? Wk : Wv;
        bb = (z == 0) ? Bq : (z == 1) ? Bk : Bv;
        op = (z == 0) ? g_Q : (z == 1) ? g_K : g_V;
    } else {
        W = Wq; bb = Bq; op = out;
    }

    int mBase = blockIdx.y * 128, nBase = blockIdx.x * 64;
    int tid = threadIdx.x, warp = tid >> 5, lane = tid & 31;
    int wm = warp >> 1, wn = warp & 1, g = lane >> 2, t = lane & 3;

    float acc[2][4][4];
#pragma unroll
    for (int a = 0; a < 2; a++)
#pragma unroll
        for (int b = 0; b < 4; b++)
#pragma unroll
            for (int c = 0; c < 4; c++) acc[a][b][c] = 0.f;

    for (int kb = 0; kb < 512; kb += 32) {
#pragma unroll
        for (int i = 0; i < 4; i++) {
            int idx = tid + i * 256;          // 1024 float4 groups: 128 rows x 8
            int r = idx >> 3, c4 = (idx & 7) * 4;
            float4 v = *reinterpret_cast<const float4*>(Ap + (size_t)(mBase + r) * 512 + kb + c4);
            As[r][c4] = f2t(v.x); As[r][c4 + 1] = f2t(v.y);
            As[r][c4 + 2] = f2t(v.z); As[r][c4 + 3] = f2t(v.w);
        }
#pragma unroll
        for (int i = 0; i < 2; i++) {
            int idx = tid + i * 256;          // 512 groups: 64 rows x 8
            int r = idx >> 3, c4 = (idx & 7) * 4;
            float4 v = *reinterpret_cast<const float4*>(W + (size_t)(nBase + r) * 512 + kb + c4);
            Bs[r][c4] = f2t(v.x); Bs[r][c4 + 1] = f2t(v.y);
            Bs[r][c4 + 2] = f2t(v.z); Bs[r][c4 + 3] = f2t(v.w);
        }
        __syncthreads();
#pragma unroll
        for (int kk = 0; kk < 32; kk += 8) {
            unsigned af[2][4];
#pragma unroll
            for (int mi = 0; mi < 2; mi++) {
                int r0 = wm * 32 + mi * 16;
                af[mi][0] = As[r0 + g][kk + t];
                af[mi][1] = As[r0 + g + 8][kk + t];
                af[mi][2] = As[r0 + g][kk + t + 4];
                af[mi][3] = As[r0 + g + 8][kk + t + 4];
            }
#pragma unroll
            for (int ni = 0; ni < 4; ni++) {
                int c0 = wn * 32 + ni * 8;
                unsigned b0 = Bs[c0 + g][kk + t];
                unsigned b1 = Bs[c0 + g][kk + t + 4];
                mma8(acc[0][ni], af[0], b0, b1);
                mma8(acc[1][ni], af[1], b0, b1);
            }
        }
        __syncthreads();
    }

#pragma unroll
    for (int mi = 0; mi < 2; mi++) {
#pragma unroll
        for (int ni = 0; ni < 4; ni++) {
            int r = mBase + wm * 32 + mi * 16 + g;
            int c = nBase + wn * 32 + ni * 8 + 2 * t;
            float v00 = acc[mi][ni][0] + bb[c];
            float v01 = acc[mi][ni][1] + bb[c + 1];
            float v10 = acc[mi][ni][2] + bb[c];
            float v11 = acc[mi][ni][3] + bb[c + 1];
            if (MODE == 0) {
                int bi = r >> 11, s = r & 2047;
                int h = c >> 6, d = c & 63;
                size_t base = (((size_t)(bi * NH + h)) * S_LEN + s) * DA;
                op[base + d] = v00;
                op[base + d + 1] = v01;
                op[base + 8 * DA + d] = v10;       // row r+8 -> s+8
                op[base + 8 * DA + d + 1] = v11;
            } else {
                op[(size_t)r * 512 + c] = v00;
                op[(size_t)r * 512 + c + 1] = v01;
                op[(size_t)(r + 8) * 512 + c] = v10;
                op[(size_t)(r + 8) * 512 + c + 1] = v11;
            }
        }
    }
}

// ---------------------------------------------------------------------------
// Kernel 3: flash attention per (q-tile=64, head, batch). 128 threads (4 warps).
// Each warp owns 16 q-rows. TF32 mma for QK^T and PV, bias streamed from L2.
// ---------------------------------------------------------------------------
#define PSTRIDE 68
#define ATTN_SMEM (3 * 64 * PSTRIDE * 4)

__global__ __launch_bounds__(128) void k_attn() {
    extern __shared__ unsigned sm[];
    unsigned* sK = sm;                       // 64 x 68
    unsigned* sV = sm + 64 * PSTRIDE;        // 64 x 68
    unsigned* sP = sm + 2 * 64 * PSTRIDE;    // 64 x 68 (sQ during prologue)

    int tid = threadIdx.x, warp = tid >> 5, lane = tid & 31;
    int g = lane >> 2, t = lane & 3;
    int qb = blockIdx.x, h = blockIdx.y, b = blockIdx.z;
    int r0 = warp * 16;

    const float* Qp = g_Q + (((size_t)(b * NH + h)) * S_LEN + qb * 64) * DA;
    const float* Kp = g_K + ((size_t)(b * NH + h)) * S_LEN * DA;
    const float* Vp = g_V + ((size_t)(b * NH + h)) * S_LEN * DA;
    const float* biasP = g_bias + ((size_t)b * S_LEN + qb * 64) * S_LEN;

    // Stage Q tile (64x64) into sP area, convert to tf32
    for (int i = tid; i < 1024; i += 128) {
        int r = i >> 4, c4 = (i & 15) * 4;
        float4 v = *reinterpret_cast<const float4*>(Qp + (size_t)r * 64 + c4);
        *reinterpret_cast<uint4*>(sP + r * PSTRIDE + c4) =
            make_uint4(f2t(v.x), f2t(v.y), f2t(v.z), f2t(v.w));
    }
    __syncthreads();

    unsigned qf[8][4];
#pragma unroll
    for (int k8 = 0; k8 < 8; k8++) {
        int kc = k8 * 8;
        qf[k8][0] = sP[(r0 + g) * PSTRIDE + kc + t];
        qf[k8][1] = sP[(r0 + g + 8) * PSTRIDE + kc + t];
        qf[k8][2] = sP[(r0 + g) * PSTRIDE + kc + t + 4];
        qf[k8][3] = sP[(r0 + g + 8) * PSTRIDE + kc + t + 4];
    }
    __syncthreads();

    float m0 = -1e30f, m1 = -1e30f, l0 = 0.f, l1 = 0.f;
    float acc[8][4];
#pragma unroll
    for (int nb = 0; nb < 8; nb++)
#pragma unroll
        for (int j = 0; j < 4; j++) acc[nb][j] = 0.f;

    for (int kt = 0; kt < S_LEN; kt += 64) {
        // Stage K and V tiles
        for (int i = tid; i < 1024; i += 128) {
            int r = i >> 4, c4 = (i & 15) * 4;
            float4 kv = *reinterpret_cast<const float4*>(Kp + (size_t)(kt + r) * 64 + c4);
            *reinterpret_cast<uint4*>(sK + r * PSTRIDE + c4) =
                make_uint4(f2t(kv.x), f2t(kv.y), f2t(kv.z), f2t(kv.w));
            float4 vv = *reinterpret_cast<const float4*>(Vp + (size_t)(kt + r) * 64 + c4);
            *reinterpret_cast<uint4*>(sV + r * PSTRIDE + c4) =
                make_uint4(f2t(vv.x), f2t(vv.y), f2t(vv.z), f2t(vv.w));
        }
        __syncthreads();

        // S = Q K^T  (per warp: 16 rows x 64 keys)
        float sc[8][4];
#pragma unroll
        for (int nb = 0; nb < 8; nb++)
#pragma unroll
            for (int j = 0; j < 4; j++) sc[nb][j] = 0.f;
#pragma unroll
        for (int nb = 0; nb < 8; nb++) {
            int n0 = nb * 8;
#pragma unroll
            for (int k8 = 0; k8 < 8; k8++) {
                int kc = k8 * 8;
                unsigned b0 = sK[(n0 + g) * PSTRIDE + kc + t];
                unsigned b1 = sK[(n0 + g) * PSTRIDE + kc + t + 4];
                mma8(sc[nb], qf[k8], b0, b1);
            }
        }

        // scale + bias + online softmax
        const float* bp0 = biasP + (size_t)(r0 + g) * S_LEN + kt;
        const float* bp1 = bp0 + (size_t)8 * S_LEN;
        float mt0 = -1e30f, mt1 = -1e30f;
#pragma unroll
        for (int nb = 0; nb < 8; nb++) {
            int c = nb * 8 + 2 * t;
            float2 z0 = *reinterpret_cast<const float2*>(bp0 + c);
            float2 z1 = *reinterpret_cast<const float2*>(bp1 + c);
            sc[nb][0] = sc[nb][0] * 0.125f + z0.x;
            sc[nb][1] = sc[nb][1] * 0.125f + z0.y;
            sc[nb][2] = sc[nb][2] * 0.125f + z1.x;
            sc[nb][3] = sc[nb][3] * 0.125f + z1.y;
            mt0 = fmaxf(mt0, fmaxf(sc[nb][0], sc[nb][1]));
            mt1 = fmaxf(mt1, fmaxf(sc[nb][2], sc[nb][3]));
        }
        mt0 = fmaxf(mt0, __shfl_xor_sync(0xffffffffu, mt0, 1));
        mt0 = fmaxf(mt0, __shfl_xor_sync(0xffffffffu, mt0, 2));
        mt1 = fmaxf(mt1, __shfl_xor_sync(0xffffffffu, mt1, 1));
        mt1 = fmaxf(mt1, __shfl_xor_sync(0xffffffffu, mt1, 2));

        float mn0 = fmaxf(m0, mt0), mn1 = fmaxf(m1, mt1);
        float al0 = __expf(m0 - mn0), al1 = __expf(m1 - mn1);
        float rs0 = 0.f, rs1 = 0.f;
#pragma unroll
        for (int nb = 0; nb < 8; nb++) {
            float p0 = __expf(sc[nb][0] - mn0);
            float p1 = __expf(sc[nb][1] - mn0);
            float p2 = __expf(sc[nb][2] - mn1);
            float p3 = __expf(sc[nb][3] - mn1);
            rs0 += p0 + p1;
            rs1 += p2 + p3;
            int c = nb * 8 + 2 * t;
            sP[(r0 + g) * PSTRIDE + c] = f2t(p0);
            sP[(r0 + g) * PSTRIDE + c + 1] = f2t(p1);
            sP[(r0 + g + 8) * PSTRIDE + c] = f2t(p2);
            sP[(r0 + g + 8) * PSTRIDE + c + 1] = f2t(p3);
        }
        rs0 += __shfl_xor_sync(0xffffffffu, rs0, 1);
        rs0 += __shfl_xor_sync(0xffffffffu, rs0, 2);
        rs1 += __shfl_xor_sync(0xffffffffu, rs1, 1);
        rs1 += __shfl_xor_sync(0xffffffffu, rs1, 2);
        l0 = l0 * al0 + rs0;
        l1 = l1 * al1 + rs1;
        m0 = mn0; m1 = mn1;
#pragma unroll
        for (int nb = 0; nb < 8; nb++) {
            acc[nb][0] *= al0; acc[nb][1] *= al0;
            acc[nb][2] *= al1; acc[nb][3] *= al1;
        }
        __syncwarp();

        // acc += P @ V  (keys = 64, d = 64)
#pragma unroll
        for (int k8 = 0; k8 < 8; k8++) {
            int kc = k8 * 8;
            unsigned a_[4];
            a_[0] = sP[(r0 + g) * PSTRIDE + kc + t];
            a_[1] = sP[(r0 + g + 8) * PSTRIDE + kc + t];
            a_[2] = sP[(r0 + g) * PSTRIDE + kc + t + 4];
            a_[3] = sP[(r0 + g + 8) * PSTRIDE + kc + t + 4];
#pragma unroll
            for (int nb = 0; nb < 8; nb++) {
                unsigned b0 = sV[(kc + t) * PSTRIDE + nb * 8 + g];
                unsigned b1 = sV[(kc + t + 4) * PSTRIDE + nb * 8 + g];
                mma8(acc[nb], a_, b0, b1);
            }
        }
        __syncthreads();
    }

    // Epilogue: O[b, q, h*64+d] = acc / l
    float inv0 = 1.f / l0, inv1 = 1.f / l1;
    float* Op = g_O + ((size_t)b * S_LEN + qb * 64) * DM + h * DA;
#pragma unroll
    for (int nb = 0; nb < 8; nb++) {
        int c = nb * 8 + 2 * t;
        int r = r0 + g;
        Op[(size_t)r * DM + c] = acc[nb][0] * inv0;
        Op[(size_t)r * DM + c + 1] = acc[nb][1] * inv0;
        Op[(size_t)(r + 8) * DM + c] = acc[nb][2] * inv1;
        Op[(size_t)(r + 8) * DM + c + 1] = acc[nb][3] * inv1;
    }
}

// ---------------------------------------------------------------------------
extern "C" void kernel_launch(void* const* d_in, const int* in_sizes, int n_in,
                              void* d_out, int out_size) {
    const float* input = (const float*)d_in[0];
    const float* top   = (const float*)d_in[1];
    const float* top_w = (const float*)d_in[2];
    const float* top_b = (const float*)d_in[3];
    const float* wq    = (const float*)d_in[4];
    const float* bq    = (const float*)d_in[5];
    const float* wk    = (const float*)d_in[6];
    const float* bk    = (const float*)d_in[7];
    const float* wv    = (const float*)d_in[8];
    const float* bv    = (const float*)d_in[9];
    const float* wo    = (const float*)d_in[10];
    const float* bo    = (const float*)d_in[11];
    float* out = (float*)d_out;

    // 1) bias = top . top_w + top_b   (HBM-bound, ~570 MB)
    k_bias<<<32768, 256>>>(top, top_w, top_b);

    // 2) QKV projections (TF32 mma), grid.z selects q/k/v
    k_gemm<0><<<dim3(8, 32, 3), 256>>>(input, wq, bq, wk, bk, wv, bv, nullptr);

    // 3) fused flash attention with topological bias
    cudaFuncSetAttribute(k_attn, cudaFuncAttributeMaxDynamicSharedMemorySize, ATTN_SMEM);
    k_attn<<<dim3(32, 8, 2), 128, ATTN_SMEM>>>();

    // 4) output projection -> d_out
    k_gemm<1><<<dim3(8, 32, 1), 256>>>(nullptr, wo, bo, nullptr, nullptr, nullptr, nullptr, out);
}